// round 15
// baseline (speedup 1.0000x reference)
#include <cuda_runtime.h>
#include <cuda_fp16.h>
#include <math.h>

#define N_NODES 200000
#define HDIM 8
#define FIN 64
#define PNODES 160  // nodes per proj block (200000 % 160 == 0)

// ---------------- packed parameter block (constant + staging) ----------------
struct CParams {               // field order == gather segment order (all float)
    float W[3][FIN * HDIM];    // 3 x 512
    float b[3][HDIM];
    float attSrc[4][HDIM];     // t0..t3
    float attDst[4][HDIM];
    float kW[HDIM * HDIM];
    float kb[HDIM];
    float q[HDIM];
    float linW[2][HDIM];
    float linB[2];
};
__constant__ CParams cP;
__device__ CParams gStage;

// ---------------- scratch (static device globals; no allocation) -------------
// out: 4*N*8 fp16 (12.8MB) followed by den: 4*N fp32 (3.2MB), one memset
#define OUT_BYTES (4 * (size_t)N_NODES * HDIM * 2)
#define DEN_BYTES (4 * (size_t)N_NODES * 4)
__device__ __align__(16) char g_accbuf[OUT_BYTES + DEN_BYTES];
__device__ __align__(16) __half g_hsrc[3][(size_t)N_NODES * HDIM]; // fp16 h per node type
__device__ float g_A[4][(size_t)N_NODES];  // per-metapath A[n] = relu(o*inv)·linW
__device__ float g_score[4];

__device__ __forceinline__ float fast_tanh(float x)
{
    float y;
    asm("tanh.approx.f32 %0, %1;" : "=f"(y) : "f"(x));
    return y;
}

// ---------------- parameter gather (one block) --------------------------------
struct SrcPtrs { const float* p[21]; };

__global__ void gather_kernel(SrcPtrs S)
{
    const int len[21] = {512,512,512, 8,8,8, 8,8,8,8, 8,8,8,8, 64,8,8, 8,8, 1,1};
    float* dst = reinterpret_cast<float*>(&gStage);
    int off = 0;
    for (int s = 0; s < 21; s++) {
        const float* src = S.p[s];
        for (int i = threadIdx.x; i < len[s]; i += blockDim.x)
            dst[off + i] = src[i];
        off += len[s];
    }
    if (threadIdx.x < 4) g_score[threadIdx.x] = 0.f;
}

// ---------------- fused projection (all 3 node types, grid.y) ----------------
struct ProjCfg {
    const float* x[3];
    __half* hout[3];
};

__global__ __launch_bounds__(PNODES) void proj_kernel(ProjCfg C)
{
    int ty = blockIdx.y;
    const float* x = C.x[ty];
    __shared__ float4 sx[PNODES * 17];   // stride-17 float4: conflict-free
    int tid = threadIdx.x;
    size_t base = (size_t)blockIdx.x * PNODES;

    const float4* xg = reinterpret_cast<const float4*>(x + base * FIN);
#pragma unroll 4
    for (int i = tid; i < PNODES * 16; i += PNODES) {
        int row = i >> 4, k4 = i & 15;
        sx[row * 17 + k4] = __ldcs(xg + i);
    }
    __syncthreads();

    const float* W = cP.W[ty];
    float acc[HDIM];
#pragma unroll
    for (int j = 0; j < HDIM; j++) acc[j] = cP.b[ty][j];
#pragma unroll
    for (int k4 = 0; k4 < 16; k4++) {
        float4 xv = sx[tid * 17 + k4];
#pragma unroll
        for (int j = 0; j < HDIM; j++) {
            acc[j] += xv.x * W[(4 * k4 + 0) * HDIM + j]
                    + xv.y * W[(4 * k4 + 1) * HDIM + j]
                    + xv.z * W[(4 * k4 + 2) * HDIM + j]
                    + xv.w * W[(4 * k4 + 3) * HDIM + j];
        }
    }

    size_t gn = base + tid;
    __half2 hh[4];
#pragma unroll
    for (int i = 0; i < 4; i++) hh[i] = __floats2half2_rn(acc[2 * i], acc[2 * i + 1]);
    *reinterpret_cast<uint4*>(C.hout[ty] + gn * HDIM) = *reinterpret_cast<uint4*>(hh);
}

// ---------------- fused edge pass (all 4 edge types, grid.y) -----------------
struct EdgeAll {
    const int*  ei[4];
    const __half* hsrc[4];
    const __half* hdst[4];
    float* den[4];
    __half* out[4];
    int E[4];
};

__device__ __forceinline__ float dot8(const float2& f0, const float2& f1,
                                      const float2& f2, const float2& f3,
                                      const float* a)
{
    return f0.x * a[0] + f0.y * a[1] + f1.x * a[2] + f1.y * a[3]
         + f2.x * a[4] + f2.y * a[5] + f3.x * a[6] + f3.y * a[7];
}

__device__ __forceinline__ void edge_one(int r, int c,
                                         const __half* __restrict__ hsrc,
                                         const __half* __restrict__ hdst,
                                         const float* __restrict__ attS,
                                         const float* __restrict__ attD,
                                         float* __restrict__ den,
                                         __half* __restrict__ out)
{
    uint4 hv = __ldg(reinterpret_cast<const uint4*>(hsrc + (size_t)r * HDIM)); // src row
    uint4 dv = __ldg(reinterpret_cast<const uint4*>(hdst + (size_t)c * HDIM)); // dst row
    const __half2* hp = reinterpret_cast<const __half2*>(&hv);
    const __half2* dp = reinterpret_cast<const __half2*>(&dv);
    float2 f0 = __half22float2(hp[0]);
    float2 f1 = __half22float2(hp[1]);
    float2 f2 = __half22float2(hp[2]);
    float2 f3 = __half22float2(hp[3]);
    float2 g0 = __half22float2(dp[0]);
    float2 g1 = __half22float2(dp[1]);
    float2 g2 = __half22float2(dp[2]);
    float2 g3 = __half22float2(dp[3]);

    float a = dot8(f0, f1, f2, f3, attS) + dot8(g0, g1, g2, g3, attD);
    a = (a > 0.f) ? a : 0.2f * a;
    float ex = __expf(a);

    __half2 m0 = __floats2half2_rn(f0.x * ex, f0.y * ex);
    __half2 m1 = __floats2half2_rn(f1.x * ex, f1.y * ex);
    __half2 m2 = __floats2half2_rn(f2.x * ex, f2.y * ex);
    __half2 m3 = __floats2half2_rn(f3.x * ex, f3.y * ex);

    __half* op = out + (size_t)c * HDIM;
    asm volatile("red.global.add.noftz.v4.f16x2 [%0], {%1, %2, %3, %4};"
                 :: "l"(op),
                    "r"(*reinterpret_cast<unsigned*>(&m0)),
                    "r"(*reinterpret_cast<unsigned*>(&m1)),
                    "r"(*reinterpret_cast<unsigned*>(&m2)),
                    "r"(*reinterpret_cast<unsigned*>(&m3))
                 : "memory");
    atomicAdd(&den[c], ex);
}

__global__ void edge_kernel(EdgeAll A)
{
    int t = blockIdx.y;
    int E = A.E[t];
    const int*  ei  = A.ei[t];
    const __half* hsrc = A.hsrc[t];
    const __half* hdst = A.hdst[t];
    float* den = A.den[t];
    __half* out = A.out[t];

    float attS[HDIM], attD[HDIM];
#pragma unroll
    for (int j = 0; j < HDIM; j++) { attS[j] = cP.attSrc[t][j]; attD[j] = cP.attDst[t][j]; }

    int i0 = (blockIdx.x * blockDim.x + threadIdx.x) * 4;
    if (i0 + 4 <= E) {
        int4 rr = __ldcs(reinterpret_cast<const int4*>(ei + i0));
        int4 cc = __ldcs(reinterpret_cast<const int4*>(ei + E + i0));
        edge_one(rr.x, cc.x, hsrc, hdst, attS, attD, den, out);
        edge_one(rr.y, cc.y, hsrc, hdst, attS, attD, den, out);
        edge_one(rr.z, cc.z, hsrc, hdst, attS, attD, den, out);
        edge_one(rr.w, cc.w, hsrc, hdst, attS, attD, den, out);
    } else {
        for (int i = i0; i < E; i++)
            edge_one(ei[i], ei[E + i], hsrc, hdst, attS, attD, den, out);
    }
}

// ---------------- semantic score + per-node head dot (all 4 metapaths) -------
__global__ void score_kernel(const __half* __restrict__ out_base,
                             const float* __restrict__ den_base,
                             float* __restrict__ score)
{
    int g = blockIdx.y;
    const __half* o = out_base + (size_t)g * N_NODES * HDIM;
    const float* den = den_base + (size_t)g * N_NODES;
    int n = blockIdx.x * blockDim.x + threadIdx.x;
    float s = 0.f;
    if (n < N_NODES) {
        float inv = 1.f / (__ldg(&den[n]) + 1e-16f);
        uint4 hv = __ldg(reinterpret_cast<const uint4*>(o + (size_t)n * HDIM));
        const __half2* hp = reinterpret_cast<const __half2*>(&hv);
        float2 f0 = __half22float2(hp[0]);
        float2 f1 = __half22float2(hp[1]);
        float2 f2 = __half22float2(hp[2]);
        float2 f3 = __half22float2(hp[3]);
        float orl[HDIM];
        orl[0] = fmaxf(f0.x * inv, 0.f); orl[1] = fmaxf(f0.y * inv, 0.f);
        orl[2] = fmaxf(f1.x * inv, 0.f); orl[3] = fmaxf(f1.y * inv, 0.f);
        orl[4] = fmaxf(f2.x * inv, 0.f); orl[5] = fmaxf(f2.y * inv, 0.f);
        orl[6] = fmaxf(f3.x * inv, 0.f); orl[7] = fmaxf(f3.y * inv, 0.f);

        // per-node head dot for the final sigmoid (linW of this group)
        const float* lw = cP.linW[g >> 1];
        float A = 0.f;
#pragma unroll
        for (int j = 0; j < HDIM; j++) A += orl[j] * lw[j];
        g_A[g][n] = A;

#pragma unroll
        for (int j = 0; j < HDIM; j++) {
            float acc = cP.kb[j];
#pragma unroll
            for (int k = 0; k < HDIM; k++) acc += orl[k] * cP.kW[k * HDIM + j];
            s += cP.q[j] * fast_tanh(acc);
        }
    }
#pragma unroll
    for (int off = 16; off; off >>= 1) s += __shfl_xor_sync(0xffffffffu, s, off);
    __shared__ float ws[8];
    int lane = threadIdx.x & 31, wid = threadIdx.x >> 5;
    if (lane == 0) ws[wid] = s;
    __syncthreads();
    if (wid == 0) {
        s = (lane < 8) ? ws[lane] : 0.f;
#pragma unroll
        for (int off = 4; off; off >>= 1) s += __shfl_xor_sync(0xffffffffu, s, off);
        if (lane == 0) atomicAdd(&score[g], s);
    }
}

// ---------------- final heads: tiny pass over A arrays -----------------------
__global__ void final_kernel(const float* __restrict__ score,
                             float* __restrict__ pred)
{
    int n = blockIdx.x * blockDim.x + threadIdx.x;
    if (n >= N_NODES) return;

    float w[4];
#pragma unroll
    for (int g = 0; g < 2; g++) {
        float s0 = __ldg(&score[2 * g])     * (1.f / (float)N_NODES);
        float s1 = __ldg(&score[2 * g + 1]) * (1.f / (float)N_NODES);
        float m  = fmaxf(s0, s1);
        float e0 = __expf(s0 - m), e1 = __expf(s1 - m);
        float winv = 1.f / (e0 + e1);
        w[2 * g] = e0 * winv; w[2 * g + 1] = e1 * winv;
    }

    float a0 = __ldg(&g_A[0][n]);
    float a1 = __ldg(&g_A[1][n]);
    float a2 = __ldg(&g_A[2][n]);
    float a3 = __ldg(&g_A[3][n]);

    float sInd = cP.linB[0] + w[0] * a0 + w[1] * a1;
    float sOrg = cP.linB[1] + w[2] * a2 + w[3] * a3;
    pred[n]           = 1.f / (1.f + __expf(-sInd));
    pred[N_NODES + n] = 1.f / (1.f + __expf(-sOrg));
}

// -----------------------------------------------------------------------------
extern "C" void kernel_launch(void* const* d_in, const int* in_sizes, int n_in,
                              void* d_out, int out_size)
{
    // one-time stream/event creation (host resources, not device memory);
    // happens on the uncaptured correctness call, reused during capture.
    static cudaStream_t s_aux = nullptr;
    static cudaEvent_t ev_fork = nullptr, ev_join = nullptr;
    if (s_aux == nullptr) {
        cudaStreamCreateWithFlags(&s_aux, cudaStreamNonBlocking);
        cudaEventCreateWithFlags(&ev_fork, cudaEventDisableTiming);
        cudaEventCreateWithFlags(&ev_join, cudaEventDisableTiming);
    }

    char *p_accbuf; __half* p_h; float* p_score;
    cudaGetSymbolAddress((void**)&p_accbuf, g_accbuf);
    cudaGetSymbolAddress((void**)&p_h, g_hsrc);
    cudaGetSymbolAddress((void**)&p_score, g_score);
    void *a_cP, *a_stage;
    cudaGetSymbolAddress(&a_cP, cP);
    cudaGetSymbolAddress(&a_stage, gStage);

    __half* p_out = reinterpret_cast<__half*>(p_accbuf);
    float*  p_den = reinterpret_cast<float*>(p_accbuf + OUT_BYTES);

    __half* h_ind = p_h;
    __half* h_org = p_h + (size_t)N_NODES * HDIM;
    __half* h_ext = p_h + 2 * (size_t)N_NODES * HDIM;

    // ---- fork: accumulator memset on aux stream, params+proj on stream 0 ----
    cudaEventRecord(ev_fork, 0);
    cudaStreamWaitEvent(s_aux, ev_fork, 0);
    cudaMemsetAsync(p_accbuf, 0, OUT_BYTES + DEN_BYTES, s_aux);

    // ---- params: gather into staging, then ONE copy into constant bank ----
    SrcPtrs SP;
    SP.p[0]  = (const float*)d_in[7];   // W_ind
    SP.p[1]  = (const float*)d_in[9];   // W_org
    SP.p[2]  = (const float*)d_in[11];  // W_ext
    SP.p[3]  = (const float*)d_in[8];   // b_ind
    SP.p[4]  = (const float*)d_in[10];  // b_org
    SP.p[5]  = (const float*)d_in[12];  // b_ext
    // attSrc, edge types t0=org->ind, t1=ext->ind, t2=ind->org, t3=ext->org
    SP.p[6]  = (const float*)d_in[15];
    SP.p[7]  = (const float*)d_in[17];
    SP.p[8]  = (const float*)d_in[13];
    SP.p[9]  = (const float*)d_in[19];
    // attDst
    SP.p[10] = (const float*)d_in[16];
    SP.p[11] = (const float*)d_in[18];
    SP.p[12] = (const float*)d_in[14];
    SP.p[13] = (const float*)d_in[20];
    SP.p[14] = (const float*)d_in[21];  // kW
    SP.p[15] = (const float*)d_in[22];  // kb
    SP.p[16] = (const float*)d_in[23];  // q
    SP.p[17] = (const float*)d_in[24];  // lin_ind_W
    SP.p[18] = (const float*)d_in[26];  // lin_org_W
    SP.p[19] = (const float*)d_in[25];  // lin_ind_b
    SP.p[20] = (const float*)d_in[27];  // lin_org_b
    gather_kernel<<<1, 256>>>(SP);
    cudaMemcpyAsync(a_cP, a_stage, sizeof(CParams), cudaMemcpyDeviceToDevice, 0);

    // ---- projection (h rows only) ----
    ProjCfg PC;
    PC.x[0] = (const float*)d_in[0];  PC.hout[0] = h_ind;
    PC.x[1] = (const float*)d_in[1];  PC.hout[1] = h_org;
    PC.x[2] = (const float*)d_in[2];  PC.hout[2] = h_ext;

    dim3 pg(N_NODES / PNODES, 3);
    proj_kernel<<<pg, PNODES>>>(PC);

    // ---- join: edge needs both proj output and zeroed accumulators ----
    cudaEventRecord(ev_join, s_aux);
    cudaStreamWaitEvent(0, ev_join, 0);

    // ---- edges ----
    EdgeAll EA;
    EA.ei[0] = (const int*)d_in[4]; EA.E[0] = in_sizes[4] / 2; EA.hsrc[0] = h_org; EA.hdst[0] = h_ind; // org->ind
    EA.ei[1] = (const int*)d_in[5]; EA.E[1] = in_sizes[5] / 2; EA.hsrc[1] = h_ext; EA.hdst[1] = h_ind; // ext->ind
    EA.ei[2] = (const int*)d_in[3]; EA.E[2] = in_sizes[3] / 2; EA.hsrc[2] = h_ind; EA.hdst[2] = h_org; // ind->org
    EA.ei[3] = (const int*)d_in[6]; EA.E[3] = in_sizes[6] / 2; EA.hsrc[3] = h_ext; EA.hdst[3] = h_org; // ext->org
    int Emax = 0;
    for (int t = 0; t < 4; t++) {
        EA.den[t]  = p_den + (size_t)t * N_NODES;
        EA.out[t]  = p_out + (size_t)t * N_NODES * HDIM;
        if (EA.E[t] > Emax) Emax = EA.E[t];
    }
    dim3 eg((Emax / 4 + 255) / 256 + 1, 4);
    edge_kernel<<<eg, 256>>>(EA);

    // ---- semantic attention (emits per-node A too) + tiny final ----
    const int NG = (N_NODES + 255) / 256;
    dim3 sg(NG, 4);
    score_kernel<<<sg, 256>>>(p_out, p_den, p_score);

    final_kernel<<<NG, 256>>>(p_score, (float*)d_out);
}

// round 16
// speedup vs baseline: 1.0098x; 1.0098x over previous
#include <cuda_runtime.h>
#include <cuda_fp16.h>
#include <math.h>

#define N_NODES 200000
#define HDIM 8
#define FIN 64
#define PNODES 160  // nodes per proj block (200000 % 160 == 0)

// ---------------- packed parameter block (constant + staging) ----------------
struct CParams {               // field order == gather segment order (all float)
    float W[3][FIN * HDIM];    // 3 x 512
    float b[3][HDIM];
    float attSrc[4][HDIM];     // t0..t3
    float attDst[4][HDIM];
    float kW[HDIM * HDIM];
    float kb[HDIM];
    float q[HDIM];
    float linW[2][HDIM];
    float linB[2];
};
__constant__ CParams cP;
__device__ CParams gStage;

// ---------------- scratch (static device globals; no allocation) -------------
// out: 4*N*8 fp16 (12.8MB) followed by den: 4*N fp32 (3.2MB), one memset
#define OUT_BYTES (4 * (size_t)N_NODES * HDIM * 2)
#define DEN_BYTES (4 * (size_t)N_NODES * 4)
__device__ __align__(16) char g_accbuf[OUT_BYTES + DEN_BYTES];
__device__ __align__(16) __half g_hsrc[3][(size_t)N_NODES * HDIM]; // fp16 h per node type
__device__ float g_A[4][(size_t)N_NODES];  // per-metapath A[n] = relu(o*inv)·linW
__device__ float g_score[4];

__device__ __forceinline__ float fast_tanh(float x)
{
    float y;
    asm("tanh.approx.f32 %0, %1;" : "=f"(y) : "f"(x));
    return y;
}

// ---------------- parameter gather (one block) --------------------------------
struct SrcPtrs { const float* p[21]; };

__global__ void gather_kernel(SrcPtrs S)
{
    const int len[21] = {512,512,512, 8,8,8, 8,8,8,8, 8,8,8,8, 64,8,8, 8,8, 1,1};
    float* dst = reinterpret_cast<float*>(&gStage);
    int off = 0;
    for (int s = 0; s < 21; s++) {
        const float* src = S.p[s];
        for (int i = threadIdx.x; i < len[s]; i += blockDim.x)
            dst[off + i] = src[i];
        off += len[s];
    }
    if (threadIdx.x < 4) g_score[threadIdx.x] = 0.f;
}

// ---------------- fused projection (all 3 node types, grid.y) ----------------
struct ProjCfg {
    const float* x[3];
    __half* hout[3];
};

__global__ __launch_bounds__(PNODES) void proj_kernel(ProjCfg C)
{
    int ty = blockIdx.y;
    const float* x = C.x[ty];
    __shared__ float4 sx[PNODES * 17];   // stride-17 float4: conflict-free
    int tid = threadIdx.x;
    size_t base = (size_t)blockIdx.x * PNODES;

    const float4* xg = reinterpret_cast<const float4*>(x + base * FIN);
#pragma unroll 4
    for (int i = tid; i < PNODES * 16; i += PNODES) {
        int row = i >> 4, k4 = i & 15;
        sx[row * 17 + k4] = __ldcs(xg + i);
    }
    __syncthreads();

    const float* W = cP.W[ty];
    float acc[HDIM];
#pragma unroll
    for (int j = 0; j < HDIM; j++) acc[j] = cP.b[ty][j];
#pragma unroll
    for (int k4 = 0; k4 < 16; k4++) {
        float4 xv = sx[tid * 17 + k4];
#pragma unroll
        for (int j = 0; j < HDIM; j++) {
            acc[j] += xv.x * W[(4 * k4 + 0) * HDIM + j]
                    + xv.y * W[(4 * k4 + 1) * HDIM + j]
                    + xv.z * W[(4 * k4 + 2) * HDIM + j]
                    + xv.w * W[(4 * k4 + 3) * HDIM + j];
        }
    }

    size_t gn = base + tid;
    __half2 hh[4];
#pragma unroll
    for (int i = 0; i < 4; i++) hh[i] = __floats2half2_rn(acc[2 * i], acc[2 * i + 1]);
    *reinterpret_cast<uint4*>(C.hout[ty] + gn * HDIM) = *reinterpret_cast<uint4*>(hh);
}

// ---------------- fused edge pass (all 4 edge types, grid.y) -----------------
// Two-phase body: ALL gathers issued first (MLP~10), then compute + reds.
struct EdgeAll {
    const int*  ei[4];
    const __half* hsrc[4];
    const __half* hdst[4];
    float* den[4];
    __half* out[4];
    int E[4];
};

__device__ __forceinline__ float dot8(const float2& f0, const float2& f1,
                                      const float2& f2, const float2& f3,
                                      const float* a)
{
    return f0.x * a[0] + f0.y * a[1] + f1.x * a[2] + f1.y * a[3]
         + f2.x * a[4] + f2.y * a[5] + f3.x * a[6] + f3.y * a[7];
}

__device__ __forceinline__ void edge_tail(int r, int c,
                                          const __half* __restrict__ hsrc,
                                          const __half* __restrict__ hdst,
                                          const float* __restrict__ attS,
                                          const float* __restrict__ attD,
                                          float* __restrict__ den,
                                          __half* __restrict__ out)
{
    uint4 hv = __ldg(reinterpret_cast<const uint4*>(hsrc + (size_t)r * HDIM));
    uint4 dv = __ldg(reinterpret_cast<const uint4*>(hdst + (size_t)c * HDIM));
    const __half2* hp = reinterpret_cast<const __half2*>(&hv);
    const __half2* dp = reinterpret_cast<const __half2*>(&dv);
    float2 f0 = __half22float2(hp[0]), f1 = __half22float2(hp[1]);
    float2 f2 = __half22float2(hp[2]), f3 = __half22float2(hp[3]);
    float2 g0 = __half22float2(dp[0]), g1 = __half22float2(dp[1]);
    float2 g2 = __half22float2(dp[2]), g3 = __half22float2(dp[3]);
    float a = dot8(f0, f1, f2, f3, attS) + dot8(g0, g1, g2, g3, attD);
    a = (a > 0.f) ? a : 0.2f * a;
    float ex = __expf(a);
    __half2 m0 = __floats2half2_rn(f0.x * ex, f0.y * ex);
    __half2 m1 = __floats2half2_rn(f1.x * ex, f1.y * ex);
    __half2 m2 = __floats2half2_rn(f2.x * ex, f2.y * ex);
    __half2 m3 = __floats2half2_rn(f3.x * ex, f3.y * ex);
    __half* op = out + (size_t)c * HDIM;
    asm volatile("red.global.add.noftz.v4.f16x2 [%0], {%1, %2, %3, %4};"
                 :: "l"(op),
                    "r"(*reinterpret_cast<unsigned*>(&m0)),
                    "r"(*reinterpret_cast<unsigned*>(&m1)),
                    "r"(*reinterpret_cast<unsigned*>(&m2)),
                    "r"(*reinterpret_cast<unsigned*>(&m3))
                 : "memory");
    atomicAdd(&den[c], ex);
}

__global__ void edge_kernel(EdgeAll A)
{
    int t = blockIdx.y;
    int E = A.E[t];
    const int*  ei  = A.ei[t];
    const __half* hsrc = A.hsrc[t];
    const __half* hdst = A.hdst[t];
    float* den = A.den[t];
    __half* out = A.out[t];

    float attS[HDIM], attD[HDIM];
#pragma unroll
    for (int j = 0; j < HDIM; j++) { attS[j] = cP.attSrc[t][j]; attD[j] = cP.attDst[t][j]; }

    int i0 = (blockIdx.x * blockDim.x + threadIdx.x) * 4;
    if (i0 + 4 <= E) {
        int4 rr = __ldcs(reinterpret_cast<const int4*>(ei + i0));
        int4 cc = __ldcs(reinterpret_cast<const int4*>(ei + E + i0));
        int r[4] = { rr.x, rr.y, rr.z, rr.w };
        int c[4] = { cc.x, cc.y, cc.z, cc.w };

        // ---- phase 1: issue all 8 row gathers back-to-back (MLP ~8) ----
        uint4 hv[4], dv[4];
#pragma unroll
        for (int k = 0; k < 4; k++)
            hv[k] = __ldg(reinterpret_cast<const uint4*>(hsrc + (size_t)r[k] * HDIM));
#pragma unroll
        for (int k = 0; k < 4; k++)
            dv[k] = __ldg(reinterpret_cast<const uint4*>(hdst + (size_t)c[k] * HDIM));

        // ---- phase 2: compute weights, then all reds ----
        float ex[4];
        __half2 m[4][4];
#pragma unroll
        for (int k = 0; k < 4; k++) {
            const __half2* hp = reinterpret_cast<const __half2*>(&hv[k]);
            const __half2* dp = reinterpret_cast<const __half2*>(&dv[k]);
            float2 f0 = __half22float2(hp[0]), f1 = __half22float2(hp[1]);
            float2 f2 = __half22float2(hp[2]), f3 = __half22float2(hp[3]);
            float2 g0 = __half22float2(dp[0]), g1 = __half22float2(dp[1]);
            float2 g2 = __half22float2(dp[2]), g3 = __half22float2(dp[3]);
            float a = dot8(f0, f1, f2, f3, attS) + dot8(g0, g1, g2, g3, attD);
            a = (a > 0.f) ? a : 0.2f * a;
            float e = __expf(a);
            ex[k] = e;
            m[k][0] = __floats2half2_rn(f0.x * e, f0.y * e);
            m[k][1] = __floats2half2_rn(f1.x * e, f1.y * e);
            m[k][2] = __floats2half2_rn(f2.x * e, f2.y * e);
            m[k][3] = __floats2half2_rn(f3.x * e, f3.y * e);
        }
#pragma unroll
        for (int k = 0; k < 4; k++) {
            __half* op = out + (size_t)c[k] * HDIM;
            asm volatile("red.global.add.noftz.v4.f16x2 [%0], {%1, %2, %3, %4};"
                         :: "l"(op),
                            "r"(*reinterpret_cast<unsigned*>(&m[k][0])),
                            "r"(*reinterpret_cast<unsigned*>(&m[k][1])),
                            "r"(*reinterpret_cast<unsigned*>(&m[k][2])),
                            "r"(*reinterpret_cast<unsigned*>(&m[k][3]))
                         : "memory");
            atomicAdd(&den[c[k]], ex[k]);
        }
    } else {
        for (int i = i0; i < E; i++)
            edge_tail(ei[i], ei[E + i], hsrc, hdst, attS, attD, den, out);
    }
}

// ---------------- semantic score + per-node head dot (all 4 metapaths) -------
__global__ void score_kernel(const __half* __restrict__ out_base,
                             const float* __restrict__ den_base,
                             float* __restrict__ score)
{
    int g = blockIdx.y;
    const __half* o = out_base + (size_t)g * N_NODES * HDIM;
    const float* den = den_base + (size_t)g * N_NODES;
    int n = blockIdx.x * blockDim.x + threadIdx.x;
    float s = 0.f;
    if (n < N_NODES) {
        float inv = 1.f / (__ldg(&den[n]) + 1e-16f);
        uint4 hv = __ldg(reinterpret_cast<const uint4*>(o + (size_t)n * HDIM));
        const __half2* hp = reinterpret_cast<const __half2*>(&hv);
        float2 f0 = __half22float2(hp[0]);
        float2 f1 = __half22float2(hp[1]);
        float2 f2 = __half22float2(hp[2]);
        float2 f3 = __half22float2(hp[3]);
        float orl[HDIM];
        orl[0] = fmaxf(f0.x * inv, 0.f); orl[1] = fmaxf(f0.y * inv, 0.f);
        orl[2] = fmaxf(f1.x * inv, 0.f); orl[3] = fmaxf(f1.y * inv, 0.f);
        orl[4] = fmaxf(f2.x * inv, 0.f); orl[5] = fmaxf(f2.y * inv, 0.f);
        orl[6] = fmaxf(f3.x * inv, 0.f); orl[7] = fmaxf(f3.y * inv, 0.f);

        const float* lw = cP.linW[g >> 1];
        float A = 0.f;
#pragma unroll
        for (int j = 0; j < HDIM; j++) A += orl[j] * lw[j];
        g_A[g][n] = A;

#pragma unroll
        for (int j = 0; j < HDIM; j++) {
            float acc = cP.kb[j];
#pragma unroll
            for (int k = 0; k < HDIM; k++) acc += orl[k] * cP.kW[k * HDIM + j];
            s += cP.q[j] * fast_tanh(acc);
        }
    }
#pragma unroll
    for (int off = 16; off; off >>= 1) s += __shfl_xor_sync(0xffffffffu, s, off);
    __shared__ float ws[8];
    int lane = threadIdx.x & 31, wid = threadIdx.x >> 5;
    if (lane == 0) ws[wid] = s;
    __syncthreads();
    if (wid == 0) {
        s = (lane < 8) ? ws[lane] : 0.f;
#pragma unroll
        for (int off = 4; off; off >>= 1) s += __shfl_xor_sync(0xffffffffu, s, off);
        if (lane == 0) atomicAdd(&score[g], s);
    }
}

// ---------------- final heads: tiny pass over A arrays -----------------------
__global__ void final_kernel(const float* __restrict__ score,
                             float* __restrict__ pred)
{
    int n = blockIdx.x * blockDim.x + threadIdx.x;
    if (n >= N_NODES) return;

    float w[4];
#pragma unroll
    for (int g = 0; g < 2; g++) {
        float s0 = __ldg(&score[2 * g])     * (1.f / (float)N_NODES);
        float s1 = __ldg(&score[2 * g + 1]) * (1.f / (float)N_NODES);
        float m  = fmaxf(s0, s1);
        float e0 = __expf(s0 - m), e1 = __expf(s1 - m);
        float winv = 1.f / (e0 + e1);
        w[2 * g] = e0 * winv; w[2 * g + 1] = e1 * winv;
    }

    float a0 = __ldg(&g_A[0][n]);
    float a1 = __ldg(&g_A[1][n]);
    float a2 = __ldg(&g_A[2][n]);
    float a3 = __ldg(&g_A[3][n]);

    float sInd = cP.linB[0] + w[0] * a0 + w[1] * a1;
    float sOrg = cP.linB[1] + w[2] * a2 + w[3] * a3;
    pred[n]           = 1.f / (1.f + __expf(-sInd));
    pred[N_NODES + n] = 1.f / (1.f + __expf(-sOrg));
}

// -----------------------------------------------------------------------------
extern "C" void kernel_launch(void* const* d_in, const int* in_sizes, int n_in,
                              void* d_out, int out_size)
{
    char *p_accbuf; __half* p_h; float* p_score;
    cudaGetSymbolAddress((void**)&p_accbuf, g_accbuf);
    cudaGetSymbolAddress((void**)&p_h, g_hsrc);
    cudaGetSymbolAddress((void**)&p_score, g_score);
    void *a_cP, *a_stage;
    cudaGetSymbolAddress(&a_cP, cP);
    cudaGetSymbolAddress(&a_stage, gStage);

    __half* p_out = reinterpret_cast<__half*>(p_accbuf);
    float*  p_den = reinterpret_cast<float*>(p_accbuf + OUT_BYTES);

    __half* h_ind = p_h;
    __half* h_org = p_h + (size_t)N_NODES * HDIM;
    __half* h_ext = p_h + 2 * (size_t)N_NODES * HDIM;

    // ---- params: gather into staging, then ONE copy into constant bank ----
    SrcPtrs SP;
    SP.p[0]  = (const float*)d_in[7];   // W_ind
    SP.p[1]  = (const float*)d_in[9];   // W_org
    SP.p[2]  = (const float*)d_in[11];  // W_ext
    SP.p[3]  = (const float*)d_in[8];   // b_ind
    SP.p[4]  = (const float*)d_in[10];  // b_org
    SP.p[5]  = (const float*)d_in[12];  // b_ext
    // attSrc, edge types t0=org->ind, t1=ext->ind, t2=ind->org, t3=ext->org
    SP.p[6]  = (const float*)d_in[15];
    SP.p[7]  = (const float*)d_in[17];
    SP.p[8]  = (const float*)d_in[13];
    SP.p[9]  = (const float*)d_in[19];
    // attDst
    SP.p[10] = (const float*)d_in[16];
    SP.p[11] = (const float*)d_in[18];
    SP.p[12] = (const float*)d_in[14];
    SP.p[13] = (const float*)d_in[20];
    SP.p[14] = (const float*)d_in[21];  // kW
    SP.p[15] = (const float*)d_in[22];  // kb
    SP.p[16] = (const float*)d_in[23];  // q
    SP.p[17] = (const float*)d_in[24];  // lin_ind_W
    SP.p[18] = (const float*)d_in[26];  // lin_org_W
    SP.p[19] = (const float*)d_in[25];  // lin_ind_b
    SP.p[20] = (const float*)d_in[27];  // lin_org_b
    gather_kernel<<<1, 256>>>(SP);
    cudaMemcpyAsync(a_cP, a_stage, sizeof(CParams), cudaMemcpyDeviceToDevice, 0);

    cudaMemsetAsync(p_accbuf, 0, OUT_BYTES + DEN_BYTES, 0);

    // ---- projection (h rows only) ----
    ProjCfg PC;
    PC.x[0] = (const float*)d_in[0];  PC.hout[0] = h_ind;
    PC.x[1] = (const float*)d_in[1];  PC.hout[1] = h_org;
    PC.x[2] = (const float*)d_in[2];  PC.hout[2] = h_ext;

    dim3 pg(N_NODES / PNODES, 3);
    proj_kernel<<<pg, PNODES>>>(PC);

    // ---- edges ----
    EdgeAll EA;
    EA.ei[0] = (const int*)d_in[4]; EA.E[0] = in_sizes[4] / 2; EA.hsrc[0] = h_org; EA.hdst[0] = h_ind; // org->ind
    EA.ei[1] = (const int*)d_in[5]; EA.E[1] = in_sizes[5] / 2; EA.hsrc[1] = h_ext; EA.hdst[1] = h_ind; // ext->ind
    EA.ei[2] = (const int*)d_in[3]; EA.E[2] = in_sizes[3] / 2; EA.hsrc[2] = h_ind; EA.hdst[2] = h_org; // ind->org
    EA.ei[3] = (const int*)d_in[6]; EA.E[3] = in_sizes[6] / 2; EA.hsrc[3] = h_ext; EA.hdst[3] = h_org; // ext->org
    int Emax = 0;
    for (int t = 0; t < 4; t++) {
        EA.den[t]  = p_den + (size_t)t * N_NODES;
        EA.out[t]  = p_out + (size_t)t * N_NODES * HDIM;
        if (EA.E[t] > Emax) Emax = EA.E[t];
    }
    dim3 eg((Emax + 1023) / 1024, 4);   // exact ceil for 4 edges x 256 threads
    edge_kernel<<<eg, 256>>>(EA);

    // ---- semantic attention (emits per-node A too) + tiny final ----
    const int NG = (N_NODES + 255) / 256;
    dim3 sg(NG, 4);
    score_kernel<<<sg, 256>>>(p_out, p_den, p_score);

    final_kernel<<<NG, 256>>>(p_score, (float*)d_out);
}

// round 17
// speedup vs baseline: 1.0099x; 1.0001x over previous
#include <cuda_runtime.h>
#include <cuda_fp16.h>
#include <math.h>

#define N_NODES 200000
#define HDIM 8
#define FIN 64
#define PNODES 160  // nodes per proj block (200000 % 160 == 0)

// ---------------- packed parameter block (constant + staging) ----------------
struct CParams {               // field order == gather segment order (all float)
    float W[3][FIN * HDIM];    // 3 x 512
    float b[3][HDIM];
    float attSrc[4][HDIM];     // t0..t3
    float attDst[4][HDIM];
    float kW[HDIM * HDIM];
    float kb[HDIM];
    float q[HDIM];
    float linW[2][HDIM];
    float linB[2];
};
__constant__ CParams cP;
__device__ CParams gStage;

// ---------------- scratch (static device globals; no allocation) -------------
// out (4*N*8 fp16) | den (4*N fp32) | score (4 fp32) — ONE memset covers all
#define OUT_BYTES (4 * (size_t)N_NODES * HDIM * 2)
#define DEN_BYTES (4 * (size_t)N_NODES * 4)
#define ACC_BYTES (OUT_BYTES + DEN_BYTES + 16)
__device__ __align__(16) char g_accbuf[ACC_BYTES];
__device__ __align__(16) __half g_hsrc[3][(size_t)N_NODES * HDIM]; // fp16 h per node type
__device__ float g_A[4][(size_t)N_NODES];  // per-metapath A[n] = relu(o*inv)·linW

__device__ __forceinline__ float fast_tanh(float x)
{
    float y;
    asm("tanh.approx.f32 %0, %1;" : "=f"(y) : "f"(x));
    return y;
}

// ---------------- parameter gather (one block) --------------------------------
struct SrcPtrs { const float* p[21]; };

__global__ void gather_kernel(SrcPtrs S)
{
    const int len[21] = {512,512,512, 8,8,8, 8,8,8,8, 8,8,8,8, 64,8,8, 8,8, 1,1};
    float* dst = reinterpret_cast<float*>(&gStage);
    int off = 0;
    for (int s = 0; s < 21; s++) {
        const float* src = S.p[s];
        for (int i = threadIdx.x; i < len[s]; i += blockDim.x)
            dst[off + i] = src[i];
        off += len[s];
    }
}

// ---------------- fused projection (all 3 node types, grid.y) ----------------
// fp16 smem staging: halves smem (more CTAs/SM) and halves compute-side LDS.
struct ProjCfg {
    const float* x[3];
    __half* hout[3];
};

__global__ __launch_bounds__(PNODES) void proj_kernel(ProjCfg C)
{
    int ty = blockIdx.y;
    const float* x = C.x[ty];
    // per node: 64 fp16 = 8 uint4, padded to 9 uint4 (144B row: conflict-free
    // for both 8B staging stores and 16B compute loads in quarter-warp phases)
    __shared__ uint4 sx4[PNODES * 9];
    int tid = threadIdx.x;
    size_t base = (size_t)blockIdx.x * PNODES;

    const float4* xg = reinterpret_cast<const float4*>(x + base * FIN);
    char* sb = reinterpret_cast<char*>(sx4);
#pragma unroll 4
    for (int i = tid; i < PNODES * 16; i += PNODES) {
        int row = i >> 4, k4 = i & 15;
        float4 v = __ldcs(xg + i);
        __half2 h0 = __floats2half2_rn(v.x, v.y);
        __half2 h1 = __floats2half2_rn(v.z, v.w);
        uint2 pk = make_uint2(*reinterpret_cast<unsigned*>(&h0),
                              *reinterpret_cast<unsigned*>(&h1));
        *reinterpret_cast<uint2*>(sb + row * 144 + k4 * 8) = pk;
    }
    __syncthreads();

    const float* W = cP.W[ty];
    float acc[HDIM];
#pragma unroll
    for (int j = 0; j < HDIM; j++) acc[j] = cP.b[ty][j];

    const uint4* rowp = reinterpret_cast<const uint4*>(sb + tid * 144);
#pragma unroll
    for (int q = 0; q < 8; q++) {
        uint4 u = rowp[q];
        const __half2* hp = reinterpret_cast<const __half2*>(&u);
#pragma unroll
        for (int p = 0; p < 4; p++) {
            float2 f = __half22float2(hp[p]);
            int k = q * 8 + p * 2;
#pragma unroll
            for (int j = 0; j < HDIM; j++)
                acc[j] += f.x * W[k * HDIM + j] + f.y * W[(k + 1) * HDIM + j];
        }
    }

    size_t gn = base + tid;
    __half2 hh[4];
#pragma unroll
    for (int i = 0; i < 4; i++) hh[i] = __floats2half2_rn(acc[2 * i], acc[2 * i + 1]);
    *reinterpret_cast<uint4*>(C.hout[ty] + gn * HDIM) = *reinterpret_cast<uint4*>(hh);
}

// ---------------- fused edge pass (all 4 edge types, grid.y) -----------------
struct EdgeAll {
    const int*  ei[4];
    const __half* hsrc[4];
    const __half* hdst[4];
    float* den[4];
    __half* out[4];
    int E[4];
};

__device__ __forceinline__ float dot8(const float2& f0, const float2& f1,
                                      const float2& f2, const float2& f3,
                                      const float* a)
{
    return f0.x * a[0] + f0.y * a[1] + f1.x * a[2] + f1.y * a[3]
         + f2.x * a[4] + f2.y * a[5] + f3.x * a[6] + f3.y * a[7];
}

__device__ __forceinline__ void edge_tail(int r, int c,
                                          const __half* __restrict__ hsrc,
                                          const __half* __restrict__ hdst,
                                          const float* __restrict__ attS,
                                          const float* __restrict__ attD,
                                          float* __restrict__ den,
                                          __half* __restrict__ out)
{
    uint4 hv = __ldg(reinterpret_cast<const uint4*>(hsrc + (size_t)r * HDIM));
    uint4 dv = __ldg(reinterpret_cast<const uint4*>(hdst + (size_t)c * HDIM));
    const __half2* hp = reinterpret_cast<const __half2*>(&hv);
    const __half2* dp = reinterpret_cast<const __half2*>(&dv);
    float2 f0 = __half22float2(hp[0]), f1 = __half22float2(hp[1]);
    float2 f2 = __half22float2(hp[2]), f3 = __half22float2(hp[3]);
    float2 g0 = __half22float2(dp[0]), g1 = __half22float2(dp[1]);
    float2 g2 = __half22float2(dp[2]), g3 = __half22float2(dp[3]);
    float a = dot8(f0, f1, f2, f3, attS) + dot8(g0, g1, g2, g3, attD);
    a = (a > 0.f) ? a : 0.2f * a;
    float ex = __expf(a);
    __half2 m0 = __floats2half2_rn(f0.x * ex, f0.y * ex);
    __half2 m1 = __floats2half2_rn(f1.x * ex, f1.y * ex);
    __half2 m2 = __floats2half2_rn(f2.x * ex, f2.y * ex);
    __half2 m3 = __floats2half2_rn(f3.x * ex, f3.y * ex);
    __half* op = out + (size_t)c * HDIM;
    asm volatile("red.global.add.noftz.v4.f16x2 [%0], {%1, %2, %3, %4};"
                 :: "l"(op),
                    "r"(*reinterpret_cast<unsigned*>(&m0)),
                    "r"(*reinterpret_cast<unsigned*>(&m1)),
                    "r"(*reinterpret_cast<unsigned*>(&m2)),
                    "r"(*reinterpret_cast<unsigned*>(&m3))
                 : "memory");
    atomicAdd(&den[c], ex);
}

__global__ void edge_kernel(EdgeAll A)
{
    int t = blockIdx.y;
    int E = A.E[t];
    const int*  ei  = A.ei[t];
    const __half* hsrc = A.hsrc[t];
    const __half* hdst = A.hdst[t];
    float* den = A.den[t];
    __half* out = A.out[t];

    float attS[HDIM], attD[HDIM];
#pragma unroll
    for (int j = 0; j < HDIM; j++) { attS[j] = cP.attSrc[t][j]; attD[j] = cP.attDst[t][j]; }

    int i0 = (blockIdx.x * blockDim.x + threadIdx.x) * 4;
    if (i0 + 4 <= E) {
        int4 rr = __ldcs(reinterpret_cast<const int4*>(ei + i0));
        int4 cc = __ldcs(reinterpret_cast<const int4*>(ei + E + i0));
        int r[4] = { rr.x, rr.y, rr.z, rr.w };
        int c[4] = { cc.x, cc.y, cc.z, cc.w };

        uint4 hv[4], dv[4];
#pragma unroll
        for (int k = 0; k < 4; k++)
            hv[k] = __ldg(reinterpret_cast<const uint4*>(hsrc + (size_t)r[k] * HDIM));
#pragma unroll
        for (int k = 0; k < 4; k++)
            dv[k] = __ldg(reinterpret_cast<const uint4*>(hdst + (size_t)c[k] * HDIM));

        float ex[4];
        __half2 m[4][4];
#pragma unroll
        for (int k = 0; k < 4; k++) {
            const __half2* hp = reinterpret_cast<const __half2*>(&hv[k]);
            const __half2* dp = reinterpret_cast<const __half2*>(&dv[k]);
            float2 f0 = __half22float2(hp[0]), f1 = __half22float2(hp[1]);
            float2 f2 = __half22float2(hp[2]), f3 = __half22float2(hp[3]);
            float2 g0 = __half22float2(dp[0]), g1 = __half22float2(dp[1]);
            float2 g2 = __half22float2(dp[2]), g3 = __half22float2(dp[3]);
            float a = dot8(f0, f1, f2, f3, attS) + dot8(g0, g1, g2, g3, attD);
            a = (a > 0.f) ? a : 0.2f * a;
            float e = __expf(a);
            ex[k] = e;
            m[k][0] = __floats2half2_rn(f0.x * e, f0.y * e);
            m[k][1] = __floats2half2_rn(f1.x * e, f1.y * e);
            m[k][2] = __floats2half2_rn(f2.x * e, f2.y * e);
            m[k][3] = __floats2half2_rn(f3.x * e, f3.y * e);
        }
#pragma unroll
        for (int k = 0; k < 4; k++) {
            __half* op = out + (size_t)c[k] * HDIM;
            asm volatile("red.global.add.noftz.v4.f16x2 [%0], {%1, %2, %3, %4};"
                         :: "l"(op),
                            "r"(*reinterpret_cast<unsigned*>(&m[k][0])),
                            "r"(*reinterpret_cast<unsigned*>(&m[k][1])),
                            "r"(*reinterpret_cast<unsigned*>(&m[k][2])),
                            "r"(*reinterpret_cast<unsigned*>(&m[k][3]))
                         : "memory");
            atomicAdd(&den[c[k]], ex[k]);
        }
    } else {
        for (int i = i0; i < E; i++)
            edge_tail(ei[i], ei[E + i], hsrc, hdst, attS, attD, den, out);
    }
}

// ---------------- semantic score + per-node head dot (all 4 metapaths) -------
__global__ void score_kernel(const __half* __restrict__ out_base,
                             const float* __restrict__ den_base,
                             float* __restrict__ score)
{
    int g = blockIdx.y;
    const __half* o = out_base + (size_t)g * N_NODES * HDIM;
    const float* den = den_base + (size_t)g * N_NODES;
    int n = blockIdx.x * blockDim.x + threadIdx.x;
    float s = 0.f;
    if (n < N_NODES) {
        float inv = 1.f / (__ldg(&den[n]) + 1e-16f);
        uint4 hv = __ldg(reinterpret_cast<const uint4*>(o + (size_t)n * HDIM));
        const __half2* hp = reinterpret_cast<const __half2*>(&hv);
        float2 f0 = __half22float2(hp[0]);
        float2 f1 = __half22float2(hp[1]);
        float2 f2 = __half22float2(hp[2]);
        float2 f3 = __half22float2(hp[3]);
        float orl[HDIM];
        orl[0] = fmaxf(f0.x * inv, 0.f); orl[1] = fmaxf(f0.y * inv, 0.f);
        orl[2] = fmaxf(f1.x * inv, 0.f); orl[3] = fmaxf(f1.y * inv, 0.f);
        orl[4] = fmaxf(f2.x * inv, 0.f); orl[5] = fmaxf(f2.y * inv, 0.f);
        orl[6] = fmaxf(f3.x * inv, 0.f); orl[7] = fmaxf(f3.y * inv, 0.f);

        const float* lw = cP.linW[g >> 1];
        float A = 0.f;
#pragma unroll
        for (int j = 0; j < HDIM; j++) A += orl[j] * lw[j];
        g_A[g][n] = A;

#pragma unroll
        for (int j = 0; j < HDIM; j++) {
            float acc = cP.kb[j];
#pragma unroll
            for (int k = 0; k < HDIM; k++) acc += orl[k] * cP.kW[k * HDIM + j];
            s += cP.q[j] * fast_tanh(acc);
        }
    }
#pragma unroll
    for (int off = 16; off; off >>= 1) s += __shfl_xor_sync(0xffffffffu, s, off);
    __shared__ float ws[8];
    int lane = threadIdx.x & 31, wid = threadIdx.x >> 5;
    if (lane == 0) ws[wid] = s;
    __syncthreads();
    if (wid == 0) {
        s = (lane < 8) ? ws[lane] : 0.f;
#pragma unroll
        for (int off = 4; off; off >>= 1) s += __shfl_xor_sync(0xffffffffu, s, off);
        if (lane == 0) atomicAdd(&score[g], s);
    }
}

// ---------------- final heads: tiny pass over A arrays -----------------------
__global__ void final_kernel(const float* __restrict__ score,
                             float* __restrict__ pred)
{
    int n = blockIdx.x * blockDim.x + threadIdx.x;
    if (n >= N_NODES) return;

    float w[4];
#pragma unroll
    for (int g = 0; g < 2; g++) {
        float s0 = __ldg(&score[2 * g])     * (1.f / (float)N_NODES);
        float s1 = __ldg(&score[2 * g + 1]) * (1.f / (float)N_NODES);
        float m  = fmaxf(s0, s1);
        float e0 = __expf(s0 - m), e1 = __expf(s1 - m);
        float winv = 1.f / (e0 + e1);
        w[2 * g] = e0 * winv; w[2 * g + 1] = e1 * winv;
    }

    float a0 = __ldg(&g_A[0][n]);
    float a1 = __ldg(&g_A[1][n]);
    float a2 = __ldg(&g_A[2][n]);
    float a3 = __ldg(&g_A[3][n]);

    float sInd = cP.linB[0] + w[0] * a0 + w[1] * a1;
    float sOrg = cP.linB[1] + w[2] * a2 + w[3] * a3;
    pred[n]           = 1.f / (1.f + __expf(-sInd));
    pred[N_NODES + n] = 1.f / (1.f + __expf(-sOrg));
}

// -----------------------------------------------------------------------------
extern "C" void kernel_launch(void* const* d_in, const int* in_sizes, int n_in,
                              void* d_out, int out_size)
{
    char *p_accbuf; __half* p_h;
    cudaGetSymbolAddress((void**)&p_accbuf, g_accbuf);
    cudaGetSymbolAddress((void**)&p_h, g_hsrc);
    void *a_cP, *a_stage;
    cudaGetSymbolAddress(&a_cP, cP);
    cudaGetSymbolAddress(&a_stage, gStage);

    __half* p_out   = reinterpret_cast<__half*>(p_accbuf);
    float*  p_den   = reinterpret_cast<float*>(p_accbuf + OUT_BYTES);
    float*  p_score = reinterpret_cast<float*>(p_accbuf + OUT_BYTES + DEN_BYTES);

    __half* h_ind = p_h;
    __half* h_org = p_h + (size_t)N_NODES * HDIM;
    __half* h_ext = p_h + 2 * (size_t)N_NODES * HDIM;

    // ---- params: gather into staging, then ONE copy into constant bank ----
    SrcPtrs SP;
    SP.p[0]  = (const float*)d_in[7];   // W_ind
    SP.p[1]  = (const float*)d_in[9];   // W_org
    SP.p[2]  = (const float*)d_in[11];  // W_ext
    SP.p[3]  = (const float*)d_in[8];   // b_ind
    SP.p[4]  = (const float*)d_in[10];  // b_org
    SP.p[5]  = (const float*)d_in[12];  // b_ext
    // attSrc, edge types t0=org->ind, t1=ext->ind, t2=ind->org, t3=ext->org
    SP.p[6]  = (const float*)d_in[15];
    SP.p[7]  = (const float*)d_in[17];
    SP.p[8]  = (const float*)d_in[13];
    SP.p[9]  = (const float*)d_in[19];
    // attDst
    SP.p[10] = (const float*)d_in[16];
    SP.p[11] = (const float*)d_in[18];
    SP.p[12] = (const float*)d_in[14];
    SP.p[13] = (const float*)d_in[20];
    SP.p[14] = (const float*)d_in[21];  // kW
    SP.p[15] = (const float*)d_in[22];  // kb
    SP.p[16] = (const float*)d_in[23];  // q
    SP.p[17] = (const float*)d_in[24];  // lin_ind_W
    SP.p[18] = (const float*)d_in[26];  // lin_org_W
    SP.p[19] = (const float*)d_in[25];  // lin_ind_b
    SP.p[20] = (const float*)d_in[27];  // lin_org_b
    gather_kernel<<<1, 256>>>(SP);
    cudaMemcpyAsync(a_cP, a_stage, sizeof(CParams), cudaMemcpyDeviceToDevice, 0);

    cudaMemsetAsync(p_accbuf, 0, ACC_BYTES, 0);   // zeroes out, den, AND score

    // ---- projection (h rows only) ----
    ProjCfg PC;
    PC.x[0] = (const float*)d_in[0];  PC.hout[0] = h_ind;
    PC.x[1] = (const float*)d_in[1];  PC.hout[1] = h_org;
    PC.x[2] = (const float*)d_in[2];  PC.hout[2] = h_ext;

    dim3 pg(N_NODES / PNODES, 3);
    proj_kernel<<<pg, PNODES>>>(PC);

    // ---- edges ----
    EdgeAll EA;
    EA.ei[0] = (const int*)d_in[4]; EA.E[0] = in_sizes[4] / 2; EA.hsrc[0] = h_org; EA.hdst[0] = h_ind; // org->ind
    EA.ei[1] = (const int*)d_in[5]; EA.E[1] = in_sizes[5] / 2; EA.hsrc[1] = h_ext; EA.hdst[1] = h_ind; // ext->ind
    EA.ei[2] = (const int*)d_in[3]; EA.E[2] = in_sizes[3] / 2; EA.hsrc[2] = h_ind; EA.hdst[2] = h_org; // ind->org
    EA.ei[3] = (const int*)d_in[6]; EA.E[3] = in_sizes[6] / 2; EA.hsrc[3] = h_ext; EA.hdst[3] = h_org; // ext->org
    int Emax = 0;
    for (int t = 0; t < 4; t++) {
        EA.den[t]  = p_den + (size_t)t * N_NODES;
        EA.out[t]  = p_out + (size_t)t * N_NODES * HDIM;
        if (EA.E[t] > Emax) Emax = EA.E[t];
    }
    dim3 eg((Emax + 1023) / 1024, 4);
    edge_kernel<<<eg, 256>>>(EA);

    // ---- semantic attention (emits per-node A too) + tiny final ----
    const int NG = (N_NODES + 255) / 256;
    dim3 sg(NG, 4);
    score_kernel<<<sg, 256>>>(p_out, p_den, p_score);

    final_kernel<<<NG, 256>>>(p_score, (float*)d_out);
}